// round 10
// baseline (speedup 1.0000x reference)
#include <cuda_runtime.h>
#include <cuda_fp16.h>

#define NN 50000
#define NE 800000
#define HID 64
#define NG 64
#define GCN_BLOCKS 1184   // 148 SMs * 8 blocks (256 thr, 18.25KB smem) = one full wave

// ---------------- persistent device scratch (allocation-free) ----------------
struct ZBlock {
    int   deg[NN];
    int   cnt[NG];
    int   ticket;
    int   pad[3];
    float pool[NG * HID];
};
__device__ ZBlock g_z;

__device__ __align__(16) __half2 g_xs1[NN * HID / 2];  // x*dinv after layer1 (fp16)
__device__ __align__(16) __half2 g_xs2[NN * HID / 2];  // x*dinv after layer2 (fp16)
__device__ __align__(16) float  g_e4s[NN * 4];         // emb[node]*dinv
__device__ float g_dinv[NN];
__device__ int   g_rowbeg[NN];
__device__ int   g_rank[NE];
__device__ int   g_col[NE];

// ---------------- packed f32x2 helpers (Blackwell FFMA2, PTX-only) ----------------
__device__ __forceinline__ unsigned long long pack2(float a, float b) {
    unsigned long long r;
    asm("mov.b64 %0, {%1, %2};" : "=l"(r)
        : "r"(__float_as_uint(a)), "r"(__float_as_uint(b)));
    return r;
}
__device__ __forceinline__ void unpack2(unsigned long long v, float& a, float& b) {
    unsigned int lo, hi;
    asm("mov.b64 {%0, %1}, %2;" : "=r"(lo), "=r"(hi) : "l"(v));
    a = __uint_as_float(lo);
    b = __uint_as_float(hi);
}
__device__ __forceinline__ void ffma2(unsigned long long& d, unsigned long long a,
                                      unsigned long long b) {
    asm("fma.rn.f32x2 %0, %1, %2, %3;" : "=l"(d) : "l"(a), "l"(b), "l"(d));
}

// ---------------- setup kernels (4 edges/thread: overlap atomic latency) ----------------
__global__ __launch_bounds__(256) void k_deg(const int* __restrict__ dst) {
    int base = blockIdx.x * 1024 + threadIdx.x;
    int e0 = base, e1 = base + 256, e2 = base + 512, e3 = base + 768;
    int d0 = (e0 < NE) ? __ldg(&dst[e0]) : -1;
    int d1 = (e1 < NE) ? __ldg(&dst[e1]) : -1;
    int d2 = (e2 < NE) ? __ldg(&dst[e2]) : -1;
    int d3 = (e3 < NE) ? __ldg(&dst[e3]) : -1;
    int r0 = (d0 >= 0) ? atomicAdd(&g_z.deg[d0], 1) : 0;
    int r1 = (d1 >= 0) ? atomicAdd(&g_z.deg[d1], 1) : 0;
    int r2 = (d2 >= 0) ? atomicAdd(&g_z.deg[d2], 1) : 0;
    int r3 = (d3 >= 0) ? atomicAdd(&g_z.deg[d3], 1) : 0;
    if (d0 >= 0) g_rank[e0] = r0;
    if (d1 >= 0) g_rank[e1] = r1;
    if (d2 >= 0) g_rank[e2] = r2;
    if (d3 >= 0) g_rank[e3] = r3;
}

// single-pass scan: per-block inclusive scan + global ticket for block base.
__global__ __launch_bounds__(256) void k_scan(const int* __restrict__ node,
                                              const float* __restrict__ emb) {
    __shared__ int sh[256];
    __shared__ int base;
    int t = threadIdx.x;
    int i = blockIdx.x * 256 + t;
    int d = (i < NN) ? g_z.deg[i] : 0;
    sh[t] = d;
    __syncthreads();
    for (int o = 1; o < 256; o <<= 1) {
        int v = (t >= o) ? sh[t - o] : 0;
        __syncthreads();
        sh[t] += v;
        __syncthreads();
    }
    if (t == 255) base = atomicAdd(&g_z.ticket, sh[255]);
    __syncthreads();
    if (i < NN) {
        g_rowbeg[i] = base + sh[t] - d;
        float di = rsqrtf((float)(d + 1));
        g_dinv[i] = di;
        float4 e = ((const float4*)emb)[node[i]];
        ((float4*)g_e4s)[i] = make_float4(e.x * di, e.y * di, e.z * di, e.w * di);
    }
}

// pure scatter, 4 edges/thread (no atomics; rank captured in k_deg)
__global__ __launch_bounds__(256) void k_fill(const int* __restrict__ src,
                                              const int* __restrict__ dst) {
    int base = blockIdx.x * 1024 + threadIdx.x;
#pragma unroll
    for (int u = 0; u < 4; u++) {
        int e = base + u * 256;
        if (e < NE) {
            int d = __ldg(&dst[e]);
            g_col[g_rowbeg[d] + g_rank[e]] = __ldg(&src[e]);
        }
    }
}

// ---------------- layer 1 fused: 8 lanes per node, 2x-unrolled gather ----------------
__global__ __launch_bounds__(256) void k_layer1(const float* __restrict__ W1,
                                                const float* __restrict__ b1,
                                                const float* __restrict__ lng,
                                                const float* __restrict__ lnb) {
    __shared__ float sW[4 * HID];   // [k][j]
    int t = threadIdx.x;
    sW[t] = W1[t];
    __syncthreads();
    int n = (blockIdx.x * 256 + t) >> 3;
    int sub = t & 7;
    if (n >= NN) return;
    const float4* e4 = (const float4*)g_e4s;
    int beg = g_rowbeg[n];
    int end = beg + g_z.deg[n];
    float ax = 0.f, ay = 0.f, az = 0.f, aw = 0.f;
    int e = beg + sub;
    for (; e + 8 < end; e += 16) {   // two in flight per lane
        int c0 = __ldg(&g_col[e]);
        int c1 = __ldg(&g_col[e + 8]);
        float4 v0 = __ldg(&e4[c0]);
        float4 v1 = __ldg(&e4[c1]);
        ax += v0.x + v1.x;
        ay += v0.y + v1.y;
        az += v0.z + v1.z;
        aw += v0.w + v1.w;
    }
    if (e < end) {
        float4 v = __ldg(&e4[__ldg(&g_col[e])]);
        ax += v.x; ay += v.y; az += v.z; aw += v.w;
    }
#pragma unroll
    for (int o = 4; o; o >>= 1) {
        ax += __shfl_xor_sync(0xffffffffu, ax, o);
        ay += __shfl_xor_sync(0xffffffffu, ay, o);
        az += __shfl_xor_sync(0xffffffffu, az, o);
        aw += __shfl_xor_sync(0xffffffffu, aw, o);
    }
    float4 self = __ldg(&e4[n]);
    float di = g_dinv[n];
    ax = (ax + self.x) * di;
    ay = (ay + self.y) * di;
    az = (az + self.z) * di;
    aw = (aw + self.w) * di;
    int jb = sub * 8;
    float v[8];
    float mu = 0.f;
#pragma unroll
    for (int u = 0; u < 8; u++) {
        int j = jb + u;
        float r = fmaf(ax, sW[j], fmaf(ay, sW[64 + j],
                  fmaf(az, sW[128 + j], fmaf(aw, sW[192 + j], __ldg(&b1[j])))));
        r = fmaxf(r, 0.f);
        v[u] = r;
        mu += r;
    }
#pragma unroll
    for (int o = 4; o; o >>= 1) mu += __shfl_xor_sync(0xffffffffu, mu, o);
    mu *= (1.f / 64.f);
    float q = 0.f;
#pragma unroll
    for (int u = 0; u < 8; u++) {
        float d = v[u] - mu;
        v[u] = d;
        q = fmaf(d, d, q);
    }
#pragma unroll
    for (int o = 4; o; o >>= 1) q += __shfl_xor_sync(0xffffffffu, q, o);
    float rs = rsqrtf(q * (1.f / 64.f) + 1e-5f);
    __half2 hv[4];
#pragma unroll
    for (int u = 0; u < 4; u++) {
        int j = jb + 2 * u;
        float ox = fmaf(v[2 * u] * rs, __ldg(&lng[j]), __ldg(&lnb[j])) * di;
        float oy = fmaf(v[2 * u + 1] * rs, __ldg(&lng[j + 1]), __ldg(&lnb[j + 1])) * di;
        hv[u] = __floats2half2_rn(ox, oy);
    }
    ((float2*)g_xs1)[(size_t)n * 16 + sub * 2 + 0] = *(float2*)&hv[0];
    ((float2*)g_xs1)[(size_t)n * 16 + sub * 2 + 1] = *(float2*)&hv[2];
}

// ---------------- fused GCN layer, PERSISTENT blocks, FFMA2 projection ----------------
template <bool LN, bool POOL>
__global__ __launch_bounds__(256) void k_gcn(const __half2* __restrict__ xs,
                                             const float* __restrict__ W,
                                             const float* __restrict__ bias,
                                             const float* __restrict__ lng,
                                             const float* __restrict__ lnb,
                                             const int* __restrict__ batch,
                                             __half2* __restrict__ xs_out) {
    __shared__ float2 sWp[HID * 32];     // 16 KB, [k][lane] pairs
    __shared__ float sy[8 * HID];        // per-warp aggregated vector
    int t = threadIdx.x;
    for (int i = t; i < HID * HID; i += 256) {
        int k = i >> 6, j = i & 63;
        float w = W[i];
        if (j < 32) sWp[k * 32 + j].x = w;
        else        sWp[k * 32 + (j - 32)].y = w;
    }
    __syncthreads();
    int lane = t & 31;
    int wid = t >> 5;
    float* y = sy + wid * HID;
    const unsigned long long* wp = (const unsigned long long*)sWp;
    unsigned long long bpair = pack2(__ldg(&bias[lane]), __ldg(&bias[lane + 32]));
    int gw = blockIdx.x * 8 + wid;
    int tw = gridDim.x * 8;
    for (int n = gw; n < NN; n += tw) {
        float2 sf = __half22float2(__ldg(&xs[(size_t)n * 32 + lane]));  // self term
        float accx = sf.x, accy = sf.y;
        int beg = g_rowbeg[n];
        int end = beg + g_z.deg[n];
        int e = beg;
        int m8 = beg + ((end - beg) & ~7);
        for (; e < m8; e += 8) {
            int s0 = __ldg(&g_col[e + 0]), s1 = __ldg(&g_col[e + 1]);
            int s2 = __ldg(&g_col[e + 2]), s3 = __ldg(&g_col[e + 3]);
            int s4 = __ldg(&g_col[e + 4]), s5 = __ldg(&g_col[e + 5]);
            int s6 = __ldg(&g_col[e + 6]), s7 = __ldg(&g_col[e + 7]);
            float2 v0 = __half22float2(__ldg(&xs[(size_t)s0 * 32 + lane]));
            float2 v1 = __half22float2(__ldg(&xs[(size_t)s1 * 32 + lane]));
            float2 v2 = __half22float2(__ldg(&xs[(size_t)s2 * 32 + lane]));
            float2 v3 = __half22float2(__ldg(&xs[(size_t)s3 * 32 + lane]));
            float2 v4 = __half22float2(__ldg(&xs[(size_t)s4 * 32 + lane]));
            float2 v5 = __half22float2(__ldg(&xs[(size_t)s5 * 32 + lane]));
            float2 v6 = __half22float2(__ldg(&xs[(size_t)s6 * 32 + lane]));
            float2 v7 = __half22float2(__ldg(&xs[(size_t)s7 * 32 + lane]));
            accx += ((v0.x + v1.x) + (v2.x + v3.x)) + ((v4.x + v5.x) + (v6.x + v7.x));
            accy += ((v0.y + v1.y) + (v2.y + v3.y)) + ((v4.y + v5.y) + (v6.y + v7.y));
        }
        for (; e < end; e++) {
            int s = __ldg(&g_col[e]);
            float2 v = __half22float2(__ldg(&xs[(size_t)s * 32 + lane]));
            accx += v.x;
            accy += v.y;
        }
        float di = g_dinv[n];
        y[2 * lane] = accx * di;
        y[2 * lane + 1] = accy * di;
        __syncwarp();
        unsigned long long acc = bpair;
#pragma unroll
        for (int k4 = 0; k4 < 16; k4++) {
            float4 yv = *(const float4*)(y + 4 * k4);   // broadcast
            ffma2(acc, pack2(yv.x, yv.x), wp[(4 * k4 + 0) * 32 + lane]);
            ffma2(acc, pack2(yv.y, yv.y), wp[(4 * k4 + 1) * 32 + lane]);
            ffma2(acc, pack2(yv.z, yv.z), wp[(4 * k4 + 2) * 32 + lane]);
            ffma2(acc, pack2(yv.w, yv.w), wp[(4 * k4 + 3) * 32 + lane]);
        }
        __syncwarp();
        float a0, a1;
        unpack2(acc, a0, a1);
        float vx = fmaxf(a0, 0.f);   // output feature f0 = lane
        float vy = fmaxf(a1, 0.f);   // output feature f1 = lane + 32
        if (LN) {
            float s = vx + vy;
#pragma unroll
            for (int o = 16; o; o >>= 1) s += __shfl_xor_sync(0xffffffffu, s, o);
            float mu = s * (1.f / 64.f);
            float dx = vx - mu, dy = vy - mu;
            float q = dx * dx + dy * dy;
#pragma unroll
            for (int o = 16; o; o >>= 1) q += __shfl_xor_sync(0xffffffffu, q, o);
            float r = rsqrtf(q * (1.f / 64.f) + 1e-5f);
            vx = fmaf(dx * r, __ldg(&lng[lane]), __ldg(&lnb[lane]));
            vy = fmaf(dy * r, __ldg(&lng[lane + 32]), __ldg(&lnb[lane + 32]));
        }
        if (POOL) {
            int g = __ldg(&batch[n]);
            atomicAdd(&g_z.pool[g * HID + lane], vx);
            atomicAdd(&g_z.pool[g * HID + lane + 32], vy);
            if (lane == 0) atomicAdd(&g_z.cnt[g], 1);
        } else {
            __half* ho = (__half*)xs_out;
            ho[(size_t)n * 64 + lane] = __float2half(vx * di);
            ho[(size_t)n * 64 + lane + 32] = __float2half(vy * di);
        }
    }
}

// ---------------- final MLP ----------------
__global__ __launch_bounds__(1024) void k_mlp(const float* __restrict__ pW1,
                                              const float* __restrict__ pb1,
                                              const float* __restrict__ pW2,
                                              const float* __restrict__ pb2,
                                              float* __restrict__ out) {
    __shared__ float sp[NG * HID];
    __shared__ float sh[NG * HID];
    int t = threadIdx.x;  // 1024
    for (int i = t; i < NG * HID; i += 1024) {
        int g = i >> 6;
        float c = (float)max(g_z.cnt[g], 1);
        sp[i] = g_z.pool[i] / c;
    }
    __syncthreads();
    for (int i = t; i < NG * HID; i += 1024) {
        int g = i >> 6, j = i & 63;
        float a = pb1[j];
        for (int k = 0; k < HID; k++) a = fmaf(sp[g * HID + k], pW1[k * HID + j], a);
        sh[i] = a;
    }
    __syncthreads();
    for (int i = t; i < NG * HID; i += 1024) {
        int g = i >> 6, j = i & 63;
        float a = pb2[j];
        for (int k = 0; k < HID; k++) a = fmaf(sh[g * HID + k], pW2[k * HID + j], a);
        out[i] = a;
    }
}

// ---------------- launcher ----------------
extern "C" void kernel_launch(void* const* d_in, const int* in_sizes, int n_in,
                              void* d_out, int out_size) {
    const int* node = (const int*)d_in[0];
    const int* src = (const int*)d_in[1];
    const int* dst = (const int*)d_in[2];
    const int* batch = (const int*)d_in[3];
    const float* emb = (const float*)d_in[4];
    const float* W1 = (const float*)d_in[5];
    const float* b1 = (const float*)d_in[6];
    const float* W2 = (const float*)d_in[7];
    const float* b2 = (const float*)d_in[8];
    const float* W3 = (const float*)d_in[9];
    const float* b3 = (const float*)d_in[10];
    const float* ln1g = (const float*)d_in[11];
    const float* ln1b = (const float*)d_in[12];
    const float* ln2g = (const float*)d_in[13];
    const float* ln2b = (const float*)d_in[14];
    const float* pW1 = (const float*)d_in[15];
    const float* pb1 = (const float*)d_in[16];
    const float* pW2 = (const float*)d_in[17];
    const float* pb2 = (const float*)d_in[18];
    float* out = (float*)d_out;

    void* zptr = nullptr;
    cudaGetSymbolAddress(&zptr, g_z);
    void* xs1p = nullptr;
    cudaGetSymbolAddress(&xs1p, g_xs1);
    void* xs2p = nullptr;
    cudaGetSymbolAddress(&xs2p, g_xs2);
    __half2* xs1 = (__half2*)xs1p;
    __half2* xs2 = (__half2*)xs2p;

    cudaMemsetAsync(zptr, 0, sizeof(ZBlock));

    const int TB = 256;
    k_deg<<<(NE + 1023) / 1024, TB>>>(dst);
    k_scan<<<(NN + TB - 1) / TB, TB>>>(node, emb);
    k_fill<<<(NE + 1023) / 1024, TB>>>(src, dst);

    dim3 g8((NN * 8 + TB - 1) / TB);

    // layer 1 (8 lanes/node, 2x unrolled) -> xs1
    k_layer1<<<g8, TB>>>(W1, b1, ln1g, ln1b);
    // layer 2 fused gather+project (+LN) -> xs2, persistent blocks
    k_gcn<true, false><<<GCN_BLOCKS, TB>>>(xs1, W2, b2, ln2g, ln2b, nullptr, xs2);
    // layer 3 fused gather+project (+pool), persistent blocks
    k_gcn<false, true><<<GCN_BLOCKS, TB>>>(xs2, W3, b3, nullptr, nullptr, batch, nullptr);
    // MLP head
    k_mlp<<<1, 1024>>>(pW1, pb1, pW2, pb2, out);
}

// round 11
// speedup vs baseline: 1.0669x; 1.0669x over previous
#include <cuda_runtime.h>
#include <cuda_fp16.h>

#define NN 50000
#define NE 800000
#define HID 64
#define NG 64
#define GCN_BLOCKS 1184   // up to 8 blocks/SM (256 thr, ~18.25KB smem)

// ---------------- persistent device scratch (allocation-free) ----------------
struct ZBlock {
    int   deg[NN];
    int   cnt[NG];
    int   ticket;
    int   pad[3];
    float pool[NG * HID];
};
__device__ ZBlock g_z;

__device__ __align__(16) __half2 g_xs1[NN * HID / 2];  // x*dinv after layer1 (fp16)
__device__ __align__(16) __half2 g_xs2[NN * HID / 2];  // x*dinv after layer2 (fp16)
__device__ __align__(16) float  g_e4s[NN * 4];         // emb[node]*dinv
__device__ float g_dinv[NN];
__device__ int   g_rowbeg[NN];
__device__ int   g_rank[NE];
__device__ int   g_col[NE];

// ---------------- packed f32x2 helpers (Blackwell FFMA2, PTX-only) ----------------
__device__ __forceinline__ unsigned long long pack2(float a, float b) {
    unsigned long long r;
    asm("mov.b64 %0, {%1, %2};" : "=l"(r)
        : "r"(__float_as_uint(a)), "r"(__float_as_uint(b)));
    return r;
}
__device__ __forceinline__ void unpack2(unsigned long long v, float& a, float& b) {
    unsigned int lo, hi;
    asm("mov.b64 {%0, %1}, %2;" : "=r"(lo), "=r"(hi) : "l"(v));
    a = __uint_as_float(lo);
    b = __uint_as_float(hi);
}
__device__ __forceinline__ void ffma2(unsigned long long& d, unsigned long long a,
                                      unsigned long long b) {
    asm("fma.rn.f32x2 %0, %1, %2, %3;" : "=l"(d) : "l"(a), "l"(b), "l"(d));
}

// ---------------- setup kernels ----------------
__global__ __launch_bounds__(256) void k_deg(const int* __restrict__ dst) {
    int e = blockIdx.x * blockDim.x + threadIdx.x;
    if (e < NE) g_rank[e] = atomicAdd(&g_z.deg[dst[e]], 1);
}

// single-pass scan: per-block inclusive scan + global ticket for block base.
__global__ __launch_bounds__(256) void k_scan(const int* __restrict__ node,
                                              const float* __restrict__ emb) {
    __shared__ int sh[256];
    __shared__ int base;
    int t = threadIdx.x;
    int i = blockIdx.x * 256 + t;
    int d = (i < NN) ? g_z.deg[i] : 0;
    sh[t] = d;
    __syncthreads();
    for (int o = 1; o < 256; o <<= 1) {
        int v = (t >= o) ? sh[t - o] : 0;
        __syncthreads();
        sh[t] += v;
        __syncthreads();
    }
    if (t == 255) base = atomicAdd(&g_z.ticket, sh[255]);
    __syncthreads();
    if (i < NN) {
        g_rowbeg[i] = base + sh[t] - d;
        float di = rsqrtf((float)(d + 1));
        g_dinv[i] = di;
        float4 e = ((const float4*)emb)[node[i]];
        ((float4*)g_e4s)[i] = make_float4(e.x * di, e.y * di, e.z * di, e.w * di);
    }
}

// pure scatter (no atomics; rank captured in k_deg)
__global__ __launch_bounds__(256) void k_fill(const int* __restrict__ src,
                                              const int* __restrict__ dst) {
    int e = blockIdx.x * blockDim.x + threadIdx.x;
    if (e < NE) {
        int d = __ldg(&dst[e]);
        g_col[g_rowbeg[d] + g_rank[e]] = __ldg(&src[e]);
    }
}

// ---------------- layer 1 fused: 8 lanes per node ----------------
__global__ __launch_bounds__(256) void k_layer1(const float* __restrict__ W1,
                                                const float* __restrict__ b1,
                                                const float* __restrict__ lng,
                                                const float* __restrict__ lnb) {
    __shared__ float sW[4 * HID];   // [k][j]
    int t = threadIdx.x;
    sW[t] = W1[t];
    __syncthreads();
    int n = (blockIdx.x * 256 + t) >> 3;
    int sub = t & 7;
    if (n >= NN) return;
    const float4* e4 = (const float4*)g_e4s;
    int beg = g_rowbeg[n];
    int end = beg + g_z.deg[n];
    float ax = 0.f, ay = 0.f, az = 0.f, aw = 0.f;
    int e = beg + sub;
    for (; e + 8 < end; e += 16) {   // two in flight per lane
        int c0 = __ldg(&g_col[e]);
        int c1 = __ldg(&g_col[e + 8]);
        float4 v0 = __ldg(&e4[c0]);
        float4 v1 = __ldg(&e4[c1]);
        ax += v0.x + v1.x;
        ay += v0.y + v1.y;
        az += v0.z + v1.z;
        aw += v0.w + v1.w;
    }
    if (e < end) {
        float4 v = __ldg(&e4[__ldg(&g_col[e])]);
        ax += v.x; ay += v.y; az += v.z; aw += v.w;
    }
#pragma unroll
    for (int o = 4; o; o >>= 1) {
        ax += __shfl_xor_sync(0xffffffffu, ax, o);
        ay += __shfl_xor_sync(0xffffffffu, ay, o);
        az += __shfl_xor_sync(0xffffffffu, az, o);
        aw += __shfl_xor_sync(0xffffffffu, aw, o);
    }
    float4 self = __ldg(&e4[n]);
    float di = g_dinv[n];
    ax = (ax + self.x) * di;
    ay = (ay + self.y) * di;
    az = (az + self.z) * di;
    aw = (aw + self.w) * di;
    int jb = sub * 8;
    float v[8];
    float mu = 0.f;
#pragma unroll
    for (int u = 0; u < 8; u++) {
        int j = jb + u;
        float r = fmaf(ax, sW[j], fmaf(ay, sW[64 + j],
                  fmaf(az, sW[128 + j], fmaf(aw, sW[192 + j], __ldg(&b1[j])))));
        r = fmaxf(r, 0.f);
        v[u] = r;
        mu += r;
    }
#pragma unroll
    for (int o = 4; o; o >>= 1) mu += __shfl_xor_sync(0xffffffffu, mu, o);
    mu *= (1.f / 64.f);
    float q = 0.f;
#pragma unroll
    for (int u = 0; u < 8; u++) {
        float d = v[u] - mu;
        v[u] = d;
        q = fmaf(d, d, q);
    }
#pragma unroll
    for (int o = 4; o; o >>= 1) q += __shfl_xor_sync(0xffffffffu, q, o);
    float rs = rsqrtf(q * (1.f / 64.f) + 1e-5f);
    __half2 hv[4];
#pragma unroll
    for (int u = 0; u < 4; u++) {
        int j = jb + 2 * u;
        float ox = fmaf(v[2 * u] * rs, __ldg(&lng[j]), __ldg(&lnb[j])) * di;
        float oy = fmaf(v[2 * u + 1] * rs, __ldg(&lng[j + 1]), __ldg(&lnb[j + 1])) * di;
        hv[u] = __floats2half2_rn(ox, oy);
    }
    ((float2*)g_xs1)[(size_t)n * 16 + sub * 2 + 0] = *(float2*)&hv[0];
    ((float2*)g_xs1)[(size_t)n * 16 + sub * 2 + 1] = *(float2*)&hv[2];
}

// ---------------- fused GCN layer, PERSISTENT blocks, FFMA2 projection ----------------
// W staged as float4 quads: sWq[k/2][lane] = (W[k][l], W[k][l+32], W[k+1][l], W[k+1][l+32]).
// 16-wide gather batch covers the mean degree in one latency round.
template <bool LN, bool POOL>
__global__ __launch_bounds__(256) void k_gcn(const __half2* __restrict__ xs,
                                             const float* __restrict__ W,
                                             const float* __restrict__ bias,
                                             const float* __restrict__ lng,
                                             const float* __restrict__ lnb,
                                             const int* __restrict__ batch,
                                             __half2* __restrict__ xs_out) {
    __shared__ float4 sWq[32 * 32];      // 16 KB
    __shared__ float sy[8 * HID];        // per-warp aggregated vector
    int t = threadIdx.x;
    for (int i = t; i < HID * HID; i += 256) {
        int k = i >> 6, j = i & 63;
        float w = W[i];
        float* cell = (float*)&sWq[(k >> 1) * 32 + (j & 31)];
        cell[(k & 1) * 2 + (j >> 5)] = w;
    }
    __syncthreads();
    int lane = t & 31;
    int wid = t >> 5;
    float* y = sy + wid * HID;
    const ulonglong2* wq = (const ulonglong2*)sWq;
    unsigned long long bpair = pack2(__ldg(&bias[lane]), __ldg(&bias[lane + 32]));
    int gw = blockIdx.x * 8 + wid;
    int tw = gridDim.x * 8;
    for (int n = gw; n < NN; n += tw) {
        float2 sf = __half22float2(__ldg(&xs[(size_t)n * 32 + lane]));  // self term
        float accx = sf.x, accy = sf.y;
        int beg = g_rowbeg[n];
        int end = beg + g_z.deg[n];
        int e = beg;
        while (end - e >= 16) {      // one latency round covers mean degree
            int s[16];
#pragma unroll
            for (int u = 0; u < 16; u++) s[u] = __ldg(&g_col[e + u]);
            float2 v[16];
#pragma unroll
            for (int u = 0; u < 16; u++)
                v[u] = __half22float2(__ldg(&xs[(size_t)s[u] * 32 + lane]));
#pragma unroll
            for (int u = 0; u < 16; u++) {
                accx += v[u].x;
                accy += v[u].y;
            }
            e += 16;
        }
        if (end - e >= 8) {
            int s[8];
#pragma unroll
            for (int u = 0; u < 8; u++) s[u] = __ldg(&g_col[e + u]);
            float2 v[8];
#pragma unroll
            for (int u = 0; u < 8; u++)
                v[u] = __half22float2(__ldg(&xs[(size_t)s[u] * 32 + lane]));
#pragma unroll
            for (int u = 0; u < 8; u++) {
                accx += v[u].x;
                accy += v[u].y;
            }
            e += 8;
        }
        for (; e < end; e++) {
            int s = __ldg(&g_col[e]);
            float2 v = __half22float2(__ldg(&xs[(size_t)s * 32 + lane]));
            accx += v.x;
            accy += v.y;
        }
        float di = g_dinv[n];
        y[2 * lane] = accx * di;
        y[2 * lane + 1] = accy * di;
        __syncwarp();
        unsigned long long accA = bpair;     // even-k partial (+bias)
        unsigned long long accB = 0;         // odd-k partial
#pragma unroll
        for (int k4 = 0; k4 < 16; k4++) {
            float4 yv = *(const float4*)(y + 4 * k4);   // broadcast LDS.128
            ulonglong2 q0 = wq[(2 * k4 + 0) * 32 + lane];   // (k0 pair, k1 pair)
            ulonglong2 q1 = wq[(2 * k4 + 1) * 32 + lane];   // (k2 pair, k3 pair)
            ffma2(accA, pack2(yv.x, yv.x), q0.x);
            ffma2(accB, pack2(yv.y, yv.y), q0.y);
            ffma2(accA, pack2(yv.z, yv.z), q1.x);
            ffma2(accB, pack2(yv.w, yv.w), q1.y);
        }
        __syncwarp();
        float a0, a1, c0, c1;
        unpack2(accA, a0, a1);
        unpack2(accB, c0, c1);
        float vx = fmaxf(a0 + c0, 0.f);   // output feature f0 = lane
        float vy = fmaxf(a1 + c1, 0.f);   // output feature f1 = lane + 32
        if (LN) {
            float s = vx + vy;
#pragma unroll
            for (int o = 16; o; o >>= 1) s += __shfl_xor_sync(0xffffffffu, s, o);
            float mu = s * (1.f / 64.f);
            float dx = vx - mu, dy = vy - mu;
            float q = dx * dx + dy * dy;
#pragma unroll
            for (int o = 16; o; o >>= 1) q += __shfl_xor_sync(0xffffffffu, q, o);
            float r = rsqrtf(q * (1.f / 64.f) + 1e-5f);
            vx = fmaf(dx * r, __ldg(&lng[lane]), __ldg(&lnb[lane]));
            vy = fmaf(dy * r, __ldg(&lng[lane + 32]), __ldg(&lnb[lane + 32]));
        }
        if (POOL) {
            int g = __ldg(&batch[n]);
            atomicAdd(&g_z.pool[g * HID + lane], vx);
            atomicAdd(&g_z.pool[g * HID + lane + 32], vy);
            if (lane == 0) atomicAdd(&g_z.cnt[g], 1);
        } else {
            __half* ho = (__half*)xs_out;
            ho[(size_t)n * 64 + lane] = __float2half(vx * di);
            ho[(size_t)n * 64 + lane + 32] = __float2half(vy * di);
        }
    }
}

// ---------------- final MLP: one block per graph ----------------
__global__ __launch_bounds__(64) void k_mlp(const float* __restrict__ pW1,
                                            const float* __restrict__ pb1,
                                            const float* __restrict__ pW2,
                                            const float* __restrict__ pb2,
                                            float* __restrict__ out) {
    __shared__ float sp[HID];
    __shared__ float sh[HID];
    int g = blockIdx.x;
    int j = threadIdx.x;
    float c = (float)max(g_z.cnt[g], 1);
    sp[j] = g_z.pool[g * HID + j] / c;
    __syncthreads();
    float a = __ldg(&pb1[j]);
#pragma unroll 8
    for (int k = 0; k < HID; k++) a = fmaf(sp[k], __ldg(&pW1[k * HID + j]), a);
    sh[j] = a;
    __syncthreads();
    float b = __ldg(&pb2[j]);
#pragma unroll 8
    for (int k = 0; k < HID; k++) b = fmaf(sh[k], __ldg(&pW2[k * HID + j]), b);
    out[g * HID + j] = b;
}

// ---------------- launcher ----------------
extern "C" void kernel_launch(void* const* d_in, const int* in_sizes, int n_in,
                              void* d_out, int out_size) {
    const int* node = (const int*)d_in[0];
    const int* src = (const int*)d_in[1];
    const int* dst = (const int*)d_in[2];
    const int* batch = (const int*)d_in[3];
    const float* emb = (const float*)d_in[4];
    const float* W1 = (const float*)d_in[5];
    const float* b1 = (const float*)d_in[6];
    const float* W2 = (const float*)d_in[7];
    const float* b2 = (const float*)d_in[8];
    const float* W3 = (const float*)d_in[9];
    const float* b3 = (const float*)d_in[10];
    const float* ln1g = (const float*)d_in[11];
    const float* ln1b = (const float*)d_in[12];
    const float* ln2g = (const float*)d_in[13];
    const float* ln2b = (const float*)d_in[14];
    const float* pW1 = (const float*)d_in[15];
    const float* pb1 = (const float*)d_in[16];
    const float* pW2 = (const float*)d_in[17];
    const float* pb2 = (const float*)d_in[18];
    float* out = (float*)d_out;

    void* zptr = nullptr;
    cudaGetSymbolAddress(&zptr, g_z);
    void* xs1p = nullptr;
    cudaGetSymbolAddress(&xs1p, g_xs1);
    void* xs2p = nullptr;
    cudaGetSymbolAddress(&xs2p, g_xs2);
    __half2* xs1 = (__half2*)xs1p;
    __half2* xs2 = (__half2*)xs2p;

    cudaMemsetAsync(zptr, 0, sizeof(ZBlock));

    const int TB = 256;
    k_deg<<<(NE + TB - 1) / TB, TB>>>(dst);
    k_scan<<<(NN + TB - 1) / TB, TB>>>(node, emb);
    k_fill<<<(NE + TB - 1) / TB, TB>>>(src, dst);

    dim3 g8((NN * 8 + TB - 1) / TB);

    // layer 1 (8 lanes/node) -> xs1
    k_layer1<<<g8, TB>>>(W1, b1, ln1g, ln1b);
    // layer 2 fused gather+project (+LN) -> xs2, persistent blocks
    k_gcn<true, false><<<GCN_BLOCKS, TB>>>(xs1, W2, b2, ln2g, ln2b, nullptr, xs2);
    // layer 3 fused gather+project (+pool), persistent blocks
    k_gcn<false, true><<<GCN_BLOCKS, TB>>>(xs2, W3, b3, nullptr, nullptr, batch, nullptr);
    // MLP head: one block per graph
    k_mlp<<<NG, 64>>>(pW1, pb1, pW2, pb2, out);
}